// round 2
// baseline (speedup 1.0000x reference)
#include <cuda_runtime.h>

#define BB 8192
#define TT 2048

__device__ __forceinline__ float tanh_ap(float x) {
    float y;
    asm("tanh.approx.f32 %0, %1;" : "=f"(y) : "f"(x));
    return y;
}

// One thread = one batch element. 128 threads/block, 64 blocks -> 64 SMs,
// exactly 1 warp per SMSP (MUFU throughput is per-SMSP; sharing would halve it).
__global__ void __launch_bounds__(128, 1)
lstm_kernel(const float* __restrict__ x,
            const float* __restrict__ h0in,
            const float* __restrict__ c0in,
            const float* __restrict__ w_ih,
            const float* __restrict__ w_hh,
            const float* __restrict__ b_ih,
            const float* __restrict__ b_hh,
            float* __restrict__ out)
{
    const int b = blockIdx.x * blockDim.x + threadIdx.x;

    // Gate rows (torch order): [0,1]=i  [2,3]=f  [4,5]=g  [6,7]=o
    // For i,f,o we compute sigmoid via sigma(z) = 0.5*tanh(0.5 z) + 0.5,
    // folding the 0.5 into the weights/bias so the chain is just tanh+fma.
    float wi0[8], wi1[8], wh0[8], wh1[8], bs[8];
#pragma unroll
    for (int k = 0; k < 8; k++) {
        const float s = (k == 4 || k == 5) ? 1.0f : 0.5f;
        wi0[k] = s * __ldg(&w_ih[2*k+0]);
        wi1[k] = s * __ldg(&w_ih[2*k+1]);
        wh0[k] = s * __ldg(&w_hh[2*k+0]);
        wh1[k] = s * __ldg(&w_hh[2*k+1]);
        bs[k]  = s * (__ldg(&b_ih[k]) + __ldg(&b_hh[k]));
    }

    float h_0 = h0in[2*b+0], h_1 = h0in[2*b+1];
    float c_0 = c0in[2*b+0], c_1 = c0in[2*b+1];
    float hc0 = 0.5f * c_0,  hc1 = 0.5f * c_1;   // running 0.5*c (off critical path)

    // x row for this batch: contiguous T*D = 4096 floats = 16 KB, 16B-aligned.
    const float4* __restrict__ xr =
        reinterpret_cast<const float4*>(x) + (size_t)b * (TT * 2 / 4);

    // Chunk = 16 timesteps = 8 float4 per thread; double-buffered prefetch.
    float4 buf[2][8];
#pragma unroll
    for (int q = 0; q < 8; q++) buf[0][q] = __ldg(&xr[q]);

#pragma unroll 1
    for (int ch = 0; ch < TT / 16; ch++) {
        const int nb = (ch + 1) & 1;
        if (ch + 1 < TT / 16) {
#pragma unroll
            for (int q = 0; q < 8; q++) buf[nb][q] = __ldg(&xr[(ch + 1) * 8 + q]);
        }
#pragma unroll
        for (int s2 = 0; s2 < 8; s2++) {
            const float4 v = buf[ch & 1][s2];
#pragma unroll
            for (int half = 0; half < 2; half++) {
                const float x0 = half ? v.z : v.x;
                const float x1 = half ? v.w : v.y;

                // z_k: x/bias terms first, h terms LAST (h is the late operand:
                // keeps the h->z depth at 2 fma = 8 cyc on the critical path).
                float z[8];
#pragma unroll
                for (int k = 0; k < 8; k++) {
                    float t = fmaf(x1, wi1[k], bs[k]);
                    t = fmaf(x0, wi0[k], t);
                    t = fmaf(h_1, wh1[k], t);
                    t = fmaf(h_0, wh0[k], t);
                    z[k] = t;
                }

                const float ti0 = tanh_ap(z[0]), ti1 = tanh_ap(z[1]);
                const float tf0 = tanh_ap(z[2]), tf1 = tanh_ap(z[3]);
                const float tg0 = tanh_ap(z[4]), tg1 = tanh_ap(z[5]);
                const float to0 = tanh_ap(z[6]), to1 = tanh_ap(z[7]);

                const float si0 = fmaf(0.5f, ti0, 0.5f);
                const float si1 = fmaf(0.5f, ti1, 0.5f);
                const float so0 = fmaf(0.5f, to0, 0.5f);
                const float so1 = fmaf(0.5f, to1, 0.5f);

                // c' = sigma(f)*c + sigma(i)*tanh(g)
                //    = (0.5c)*t_f + (0.5c + sigma(i)*t_g)
                // -> only ONE fma after tanh(f) on the critical path.
                const float q0 = fmaf(si0, tg0, hc0);
                const float q1 = fmaf(si1, tg1, hc1);
                c_0 = fmaf(hc0, tf0, q0);
                c_1 = fmaf(hc1, tf1, q1);

                const float tc0 = tanh_ap(c_0);
                const float tc1 = tanh_ap(c_1);
                h_0 = so0 * tc0;
                h_1 = so1 * tc1;
                hc0 = 0.5f * c_0;
                hc1 = 0.5f * c_1;
            }
        }
    }

    out[2*b+0] = c_0;
    out[2*b+1] = c_1;
}

extern "C" void kernel_launch(void* const* d_in, const int* in_sizes, int n_in,
                              void* d_out, int out_size) {
    const float* x    = (const float*)d_in[0];
    const float* h0   = (const float*)d_in[1];
    const float* c0   = (const float*)d_in[2];
    const float* w_ih = (const float*)d_in[3];
    const float* w_hh = (const float*)d_in[4];
    const float* b_ih = (const float*)d_in[5];
    const float* b_hh = (const float*)d_in[6];
    lstm_kernel<<<BB / 128, 128>>>(x, h0, c0, w_ih, w_hh, b_ih, b_hh,
                                   (float*)d_out);
}

// round 3
// speedup vs baseline: 1.0060x; 1.0060x over previous
#include <cuda_runtime.h>

#define BB 8192
#define TT 2048

__device__ __forceinline__ float tanh_ap(float x) {
    float y;
    asm("tanh.approx.f32 %0, %1;" : "=f"(y) : "f"(x));
    return y;
}

// One thread = one batch element. 128 threads/block, 64 blocks -> 64 SMs,
// exactly 1 warp per SMSP (MUFU throughput is per-SMSP; sharing would halve it).
__global__ void __launch_bounds__(128, 1)
lstm_kernel(const float* __restrict__ x,
            const float* __restrict__ h0in,
            const float* __restrict__ c0in,
            const float* __restrict__ w_ih,
            const float* __restrict__ w_hh,
            const float* __restrict__ b_ih,
            const float* __restrict__ b_hh,
            float* __restrict__ out)
{
    const int b = blockIdx.x * blockDim.x + threadIdx.x;

    // Gate rows (torch order): [0,1]=i  [2,3]=f  [4,5]=g  [6,7]=o
    // For i,f,o we compute sigmoid via sigma(z) = 0.5*tanh(0.5 z) + 0.5,
    // folding the 0.5 into the weights/bias so the chain is just tanh+fma.
    float wi0[8], wi1[8], wh0[8], wh1[8], bs[8];
#pragma unroll
    for (int k = 0; k < 8; k++) {
        const float s = (k == 4 || k == 5) ? 1.0f : 0.5f;
        wi0[k] = s * __ldg(&w_ih[2*k+0]);
        wi1[k] = s * __ldg(&w_ih[2*k+1]);
        wh0[k] = s * __ldg(&w_hh[2*k+0]);
        wh1[k] = s * __ldg(&w_hh[2*k+1]);
        bs[k]  = s * (__ldg(&b_ih[k]) + __ldg(&b_hh[k]));
    }

    float h_0 = h0in[2*b+0], h_1 = h0in[2*b+1];
    float c_0 = c0in[2*b+0], c_1 = c0in[2*b+1];
    float hc0 = 0.5f * c_0,  hc1 = 0.5f * c_1;   // running 0.5*c (off critical path)

    // x row for this batch: contiguous T*D = 4096 floats = 16 KB, 16B-aligned.
    const float4* __restrict__ xr =
        reinterpret_cast<const float4*>(x) + (size_t)b * (TT * 2 / 4);

    // Chunk = 16 timesteps = 8 float4 per thread; double-buffered prefetch.
    float4 buf[2][8];
#pragma unroll
    for (int q = 0; q < 8; q++) buf[0][q] = __ldg(&xr[q]);

#pragma unroll 1
    for (int ch = 0; ch < TT / 16; ch++) {
        const int nb = (ch + 1) & 1;
        if (ch + 1 < TT / 16) {
#pragma unroll
            for (int q = 0; q < 8; q++) buf[nb][q] = __ldg(&xr[(ch + 1) * 8 + q]);
        }
#pragma unroll
        for (int s2 = 0; s2 < 8; s2++) {
            const float4 v = buf[ch & 1][s2];
#pragma unroll
            for (int half = 0; half < 2; half++) {
                const float x0 = half ? v.z : v.x;
                const float x1 = half ? v.w : v.y;

                // z_k: x/bias terms first, h terms LAST (h is the late operand:
                // keeps the h->z depth at 2 fma = 8 cyc on the critical path).
                float z[8];
#pragma unroll
                for (int k = 0; k < 8; k++) {
                    float t = fmaf(x1, wi1[k], bs[k]);
                    t = fmaf(x0, wi0[k], t);
                    t = fmaf(h_1, wh1[k], t);
                    t = fmaf(h_0, wh0[k], t);
                    z[k] = t;
                }

                const float ti0 = tanh_ap(z[0]), ti1 = tanh_ap(z[1]);
                const float tf0 = tanh_ap(z[2]), tf1 = tanh_ap(z[3]);
                const float tg0 = tanh_ap(z[4]), tg1 = tanh_ap(z[5]);
                const float to0 = tanh_ap(z[6]), to1 = tanh_ap(z[7]);

                const float si0 = fmaf(0.5f, ti0, 0.5f);
                const float si1 = fmaf(0.5f, ti1, 0.5f);
                const float so0 = fmaf(0.5f, to0, 0.5f);
                const float so1 = fmaf(0.5f, to1, 0.5f);

                // c' = sigma(f)*c + sigma(i)*tanh(g)
                //    = (0.5c)*t_f + (0.5c + sigma(i)*t_g)
                // -> only ONE fma after tanh(f) on the critical path.
                const float q0 = fmaf(si0, tg0, hc0);
                const float q1 = fmaf(si1, tg1, hc1);
                c_0 = fmaf(hc0, tf0, q0);
                c_1 = fmaf(hc1, tf1, q1);

                const float tc0 = tanh_ap(c_0);
                const float tc1 = tanh_ap(c_1);
                h_0 = so0 * tc0;
                h_1 = so1 * tc1;
                hc0 = 0.5f * c_0;
                hc1 = 0.5f * c_1;
            }
        }
    }

    out[2*b+0] = c_0;
    out[2*b+1] = c_1;
}

extern "C" void kernel_launch(void* const* d_in, const int* in_sizes, int n_in,
                              void* d_out, int out_size) {
    const float* x    = (const float*)d_in[0];
    const float* h0   = (const float*)d_in[1];
    const float* c0   = (const float*)d_in[2];
    const float* w_ih = (const float*)d_in[3];
    const float* w_hh = (const float*)d_in[4];
    const float* b_ih = (const float*)d_in[5];
    const float* b_hh = (const float*)d_in[6];
    lstm_kernel<<<BB / 128, 128>>>(x, h0, c0, w_ih, w_hh, b_ih, b_hh,
                                   (float*)d_out);
}